// round 1
// baseline (speedup 1.0000x reference)
#include <cuda_runtime.h>
#include <cuda_bf16.h>
#include <math.h>

// Problem constants (fixed by setup_inputs)
constexpr int Bsz = 2;
constexpr int T   = 2048;
constexpr int C   = 1024;
constexpr int NH  = 16;
constexpr int NKV = 8;
constexpr int HD  = 64;
constexpr int E   = 8;
constexpr int H   = 2048;
constexpr int N   = Bsz * T;          // 4096
constexpr int TOPK = 2;
constexpr int CAP = 2 * N * TOPK / E; // 2048
constexpr float EPS = 1.1920929e-07f;

// -------------------- scratch (device globals; no dynamic alloc) ----------
__device__ float g_xn [N * C];
__device__ float g_q  [N * NH * HD];
__device__ float g_k  [N * NKV * HD];
__device__ float g_v  [N * NKV * HD];
__device__ float g_y  [N * C];
__device__ float g_x2 [N * C];
__device__ float g_xn2[N * C];
__device__ float g_buf[E * CAP * C];
__device__ float g_h  [E * CAP * H];
__device__ float g_bo [E * CAP * C];
__device__ int   g_flat_e  [N * TOPK];
__device__ int   g_flat_pos[N * TOPK];
__device__ float g_flat_w  [N * TOPK];
__device__ int   g_counts  [E];

// -------------------- RMSNorm over C=1024, one block per row -------------
__global__ void rmsnorm_kernel(const float* __restrict__ x, float* __restrict__ xn) {
    int n = blockIdx.x, tid = threadIdx.x;  // 256 threads
    const float4* xp = (const float4*)(x + (size_t)n * C);
    float4 v = xp[tid];
    float sq = v.x*v.x + v.y*v.y + v.z*v.z + v.w*v.w;
    #pragma unroll
    for (int o = 16; o > 0; o >>= 1) sq += __shfl_xor_sync(0xffffffffu, sq, o);
    __shared__ float red[8];
    if ((tid & 31) == 0) red[tid >> 5] = sq;
    __syncthreads();
    __shared__ float tot;
    if (tid == 0) {
        float s = 0;
        #pragma unroll
        for (int i = 0; i < 8; i++) s += red[i];
        tot = s;
    }
    __syncthreads();
    float r = rsqrtf(tot / (float)C + EPS);
    float4 o4 = make_float4(v.x*r, v.y*r, v.z*r, v.w*r);
    ((float4*)(xn + (size_t)n * C))[tid] = o4;
}

// -------------------- generic tiled GEMM: Cmat[M,N] = A[M,K] @ B[N,K]^T ---
// mode: 0 plain, 1 add residual, 2 relu^2 epilogue
// expert mode when counts != nullptr: per-expert strides, M=min(counts[e],CAP)
__global__ void gemm64(const float* __restrict__ A, const float* __restrict__ Bm,
                       float* __restrict__ Cm, int M, int Nn, int K,
                       int mode, const float* __restrict__ resid,
                       const int* __restrict__ counts,
                       size_t sA, size_t sB, size_t sC) {
    if (counts) {
        int e = blockIdx.z;
        A  += (size_t)e * sA;
        Bm += (size_t)e * sB;
        Cm += (size_t)e * sC;
        int cnt = counts[e];
        M = cnt < CAP ? cnt : CAP;
    }
    int row0 = blockIdx.y * 64;
    int col0 = blockIdx.x * 64;
    if (row0 >= M) return;

    __shared__ float As[16 * 68];
    __shared__ float Bs[16 * 68];
    int tid = threadIdx.x;           // 256
    int tx = tid & 15, ty = tid >> 4;
    float acc[4][4];
    #pragma unroll
    for (int i = 0; i < 4; i++)
        #pragma unroll
        for (int j = 0; j < 4; j++) acc[i][j] = 0.f;

    int lk = tid & 15, lm = tid >> 4;   // load coords: k = lk, m = lm + 16*r
    for (int k0 = 0; k0 < K; k0 += 16) {
        #pragma unroll
        for (int r = 0; r < 4; r++) {
            int m = lm + 16 * r;
            int gm = row0 + m;
            As[lk * 68 + m] = (gm < M) ? A[(size_t)gm * K + k0 + lk] : 0.f;
            int gn = col0 + m;
            Bs[lk * 68 + m] = Bm[(size_t)gn * K + k0 + lk];
        }
        __syncthreads();
        #pragma unroll
        for (int kk = 0; kk < 16; kk++) {
            float4 a4 = *(const float4*)&As[kk * 68 + ty * 4];
            float4 b4 = *(const float4*)&Bs[kk * 68 + tx * 4];
            float av[4] = {a4.x, a4.y, a4.z, a4.w};
            float bv[4] = {b4.x, b4.y, b4.z, b4.w};
            #pragma unroll
            for (int i = 0; i < 4; i++)
                #pragma unroll
                for (int j = 0; j < 4; j++) acc[i][j] += av[i] * bv[j];
        }
        __syncthreads();
    }
    #pragma unroll
    for (int i = 0; i < 4; i++) {
        int gm = row0 + ty * 4 + i;
        if (gm >= M) continue;
        #pragma unroll
        for (int j = 0; j < 4; j++) {
            int gn = col0 + tx * 4 + j;
            size_t idx = (size_t)gm * Nn + gn;
            float v = acc[i][j];
            if (mode == 1) v += resid[idx];
            else if (mode == 2) { v = v > 0.f ? v : 0.f; v = v * v; }
            Cm[idx] = v;
        }
    }
}

// -------------------- gate = 2*sigmoid(xn[:, :32] @ gw^T); v += gate*ve ---
__global__ void gate_kernel(const float* __restrict__ xn, const float* __restrict__ ve,
                            const float* __restrict__ gw, float* __restrict__ v) {
    int n = blockIdx.x, tid = threadIdx.x;   // 256
    __shared__ float g[NKV];
    int w = tid >> 5, l = tid & 31;
    float s = xn[(size_t)n * C + l] * gw[w * 32 + l];
    #pragma unroll
    for (int o = 16; o > 0; o >>= 1) s += __shfl_xor_sync(0xffffffffu, s, o);
    if (l == 0) g[w] = 2.0f / (1.0f + __expf(-s));
    __syncthreads();
    #pragma unroll
    for (int i = tid; i < NKV * HD; i += 256)
        v[(size_t)n * (NKV * HD) + i] += g[i >> 6] * ve[(size_t)n * (NKV * HD) + i];
}

// -------------------- RoPE then RMS over hd=64, one block per head-row ----
__global__ void rope_rms_kernel(float* __restrict__ ptr, int nheads,
                                const float* __restrict__ cosp, const float* __restrict__ sinp) {
    int row = blockIdx.x;
    int t = (row / nheads) % T;
    int tid = threadIdx.x;   // 64
    __shared__ float buf[64];
    __shared__ float red[2];
    float* p = ptr + (size_t)row * HD;
    buf[tid] = p[tid];
    __syncthreads();
    float val;
    if (tid < 32) val = buf[tid] * cosp[t * 32 + tid] + buf[tid + 32] * sinp[t * 32 + tid];
    else { int j = tid - 32; val = -buf[j] * sinp[t * 32 + j] + buf[tid] * cosp[t * 32 + j]; }
    float sq = val * val;
    #pragma unroll
    for (int o = 16; o > 0; o >>= 1) sq += __shfl_xor_sync(0xffffffffu, sq, o);
    if ((tid & 31) == 0) red[tid >> 5] = sq;
    __syncthreads();
    float r = rsqrtf((red[0] + red[1]) / (float)HD + EPS);
    p[tid] = val * r;
}

// -------------------- windowed causal GQA attention -----------------------
__global__ void attn_kernel(const float* __restrict__ q, const float* __restrict__ k,
                            const float* __restrict__ v, float* __restrict__ y,
                            const int* __restrict__ pwin) {
    int t = blockIdx.x, h = blockIdx.y, b = blockIdx.z;
    int win = *pwin;
    __shared__ float qs[64];
    __shared__ float sc[1056];
    __shared__ float red[128];
    int tid = threadIdx.x;  // 128
    int hk = h / (NH / NKV);
    size_t qoff = ((size_t)(b * T + t) * NH + h) * HD;
    if (tid < 64) qs[tid] = q[qoff + tid];
    __syncthreads();
    int s0 = t - win; if (s0 < 0) s0 = 0;
    int len = t - s0 + 1;
    float lmax = -1e30f;
    for (int sl = tid; sl < len; sl += 128) {
        const float4* kp = (const float4*)(k + ((size_t)(b * T + s0 + sl) * NKV + hk) * HD);
        float dot = 0.f;
        #pragma unroll
        for (int d4 = 0; d4 < 16; d4++) {
            float4 kv4 = kp[d4];
            dot += qs[d4*4]*kv4.x + qs[d4*4+1]*kv4.y + qs[d4*4+2]*kv4.z + qs[d4*4+3]*kv4.w;
        }
        dot *= 0.125f;  // 1/sqrt(64)
        sc[sl] = dot;
        lmax = fmaxf(lmax, dot);
    }
    red[tid] = lmax; __syncthreads();
    #pragma unroll
    for (int o = 64; o > 0; o >>= 1) { if (tid < o) red[tid] = fmaxf(red[tid], red[tid + o]); __syncthreads(); }
    float m = red[0];
    __syncthreads();
    float lsum = 0.f;
    for (int sl = tid; sl < len; sl += 128) { float p = __expf(sc[sl] - m); sc[sl] = p; lsum += p; }
    red[tid] = lsum; __syncthreads();
    #pragma unroll
    for (int o = 64; o > 0; o >>= 1) { if (tid < o) red[tid] += red[tid + o]; __syncthreads(); }
    float inv = 1.0f / red[0];
    __syncthreads();
    int d = tid & 63, part = tid >> 6;
    float acc = 0.f;
    for (int sl = part; sl < len; sl += 2)
        acc += sc[sl] * v[((size_t)(b * T + s0 + sl) * NKV + hk) * HD + d];
    red[tid] = acc; __syncthreads();
    if (tid < 64) y[qoff + tid] = (red[tid] + red[tid + 64]) * inv;
}

// -------------------- router: logits, softmax -> rw out, top-2 ------------
__global__ void router_kernel(const float* __restrict__ xn2, const float* __restrict__ rw_w,
                              float* __restrict__ rw_out, int* __restrict__ flat_e,
                              float* __restrict__ flat_w) {
    int n = blockIdx.x, tid = threadIdx.x;   // 256
    int w = tid >> 5, l = tid & 31;
    __shared__ float logit[E];
    const float* xp = xn2 + (size_t)n * C;
    float s = 0.f;
    for (int i = l; i < C; i += 32) s += xp[i] * rw_w[(size_t)w * C + i];
    #pragma unroll
    for (int o = 16; o > 0; o >>= 1) s += __shfl_xor_sync(0xffffffffu, s, o);
    if (l == 0) logit[w] = s;
    __syncthreads();
    if (tid == 0) {
        float m = -1e30f;
        #pragma unroll
        for (int e = 0; e < E; e++) m = fmaxf(m, logit[e]);
        float p[E], sum = 0.f;
        #pragma unroll
        for (int e = 0; e < E; e++) { p[e] = __expf(logit[e] - m); sum += p[e]; }
        float inv = 1.0f / sum;
        #pragma unroll
        for (int e = 0; e < E; e++) { p[e] *= inv; rw_out[(size_t)n * E + e] = p[e]; }
        int b0 = 0; float v0 = p[0];
        #pragma unroll
        for (int e = 1; e < E; e++) if (p[e] > v0) { v0 = p[e]; b0 = e; }
        int b1 = -1; float v1 = -1.f;
        #pragma unroll
        for (int e = 0; e < E; e++) if (e != b0 && p[e] > v1) { v1 = p[e]; b1 = e; }
        float wsum = v0 + v1 + 1e-10f;
        flat_e[2 * n]     = b0; flat_w[2 * n]     = v0 / wsum;
        flat_e[2 * n + 1] = b1; flat_w[2 * n + 1] = v1 / wsum;
    }
}

// -------------------- per-expert stable positions (prefix scan) -----------
__global__ void pos_kernel(const int* __restrict__ flat_e, int* __restrict__ flat_pos,
                           int* __restrict__ counts) {
    int e = blockIdx.x;       // one block per expert
    int tid = threadIdx.x;    // 1024, each handles 8 flats
    __shared__ int sd[1024];
    int base_f = tid * 8;
    int loc = 0;
    #pragma unroll
    for (int i = 0; i < 8; i++) loc += (flat_e[base_f + i] == e);
    sd[tid] = loc; __syncthreads();
    for (int o = 1; o < 1024; o <<= 1) {
        int v = 0;
        if (tid >= o) v = sd[tid - o];
        __syncthreads();
        sd[tid] += v;
        __syncthreads();
    }
    int running = sd[tid] - loc;
    #pragma unroll
    for (int i = 0; i < 8; i++)
        if (flat_e[base_f + i] == e) flat_pos[base_f + i] = running++;
    if (tid == 1023) counts[e] = sd[1023];
}

// -------------------- scatter token rows into expert buffers --------------
__global__ void scatter_kernel(const float* __restrict__ xn2, const int* __restrict__ flat_e,
                               const int* __restrict__ flat_pos, float* __restrict__ buf) {
    int f = blockIdx.x, tid = threadIdx.x;  // 256
    int pos = flat_pos[f];
    if (pos >= CAP) return;
    int e = flat_e[f], token = f >> 1;
    const float4* src = (const float4*)(xn2 + (size_t)token * C);
    float4* dst = (float4*)(buf + ((size_t)e * CAP + pos) * C);
    dst[tid] = src[tid];
}

// -------------------- combine expert outputs + residual -> final out ------
__global__ void combine_kernel(const float* __restrict__ x2, const float* __restrict__ bo,
                               const int* __restrict__ flat_e, const int* __restrict__ flat_pos,
                               const float* __restrict__ flat_w, float* __restrict__ out) {
    int n = blockIdx.x, tid = threadIdx.x;  // 256
    float4 acc = ((const float4*)(x2 + (size_t)n * C))[tid];
    #pragma unroll
    for (int kk = 0; kk < TOPK; kk++) {
        int f = TOPK * n + kk;
        int pos = flat_pos[f];
        if (pos >= CAP) continue;
        float wgt = flat_w[f];
        float4 bv = ((const float4*)(bo + ((size_t)flat_e[f] * CAP + pos) * C))[tid];
        acc.x += wgt * bv.x; acc.y += wgt * bv.y; acc.z += wgt * bv.z; acc.w += wgt * bv.w;
    }
    ((float4*)(out + (size_t)n * C))[tid] = acc;
}

// ==========================================================================
extern "C" void kernel_launch(void* const* d_in, const int* in_sizes, int n_in,
                              void* d_out, int out_size) {
    const float* x    = (const float*)d_in[0];
    const float* ve   = (const float*)d_in[1];
    const float* cosp = (const float*)d_in[2];
    const float* sinp = (const float*)d_in[3];
    const float* cqw  = (const float*)d_in[4];
    const float* ckw  = (const float*)d_in[5];
    const float* cvw  = (const float*)d_in[6];
    const float* cpw  = (const float*)d_in[7];
    const float* gww  = (const float*)d_in[8];
    const float* rww  = (const float*)d_in[9];
    const float* fcw  = (const float*)d_in[10];
    const float* pjw  = (const float*)d_in[11];
    const int*   pwin = (const int*)d_in[12];
    float* out = (float*)d_out;

    float *xn, *q, *k, *v, *y, *x2, *xn2, *buf, *hbuf, *bo, *fw;
    int *fe, *fp, *cnt;
    cudaGetSymbolAddress((void**)&xn,  g_xn);
    cudaGetSymbolAddress((void**)&q,   g_q);
    cudaGetSymbolAddress((void**)&k,   g_k);
    cudaGetSymbolAddress((void**)&v,   g_v);
    cudaGetSymbolAddress((void**)&y,   g_y);
    cudaGetSymbolAddress((void**)&x2,  g_x2);
    cudaGetSymbolAddress((void**)&xn2, g_xn2);
    cudaGetSymbolAddress((void**)&buf, g_buf);
    cudaGetSymbolAddress((void**)&hbuf,g_h);
    cudaGetSymbolAddress((void**)&bo,  g_bo);
    cudaGetSymbolAddress((void**)&fe,  g_flat_e);
    cudaGetSymbolAddress((void**)&fp,  g_flat_pos);
    cudaGetSymbolAddress((void**)&fw,  g_flat_w);
    cudaGetSymbolAddress((void**)&cnt, g_counts);

    // 1) xn = rms(x)
    rmsnorm_kernel<<<N, 256>>>(x, xn);
    // 2) q,k,v projections
    gemm64<<<dim3(NH*HD/64,  N/64), 256>>>(xn, cqw, q, N, NH*HD,  C, 0, nullptr, nullptr, 0,0,0);
    gemm64<<<dim3(NKV*HD/64, N/64), 256>>>(xn, ckw, k, N, NKV*HD, C, 0, nullptr, nullptr, 0,0,0);
    gemm64<<<dim3(NKV*HD/64, N/64), 256>>>(xn, cvw, v, N, NKV*HD, C, 0, nullptr, nullptr, 0,0,0);
    // 3) v += gate * ve
    gate_kernel<<<N, 256>>>(xn, ve, gww, v);
    // 4) rope + rms on q, k
    rope_rms_kernel<<<N*NH,  64>>>(q, NH,  cosp, sinp);
    rope_rms_kernel<<<N*NKV, 64>>>(k, NKV, cosp, sinp);
    // 5) attention
    attn_kernel<<<dim3(T, NH, Bsz), 128>>>(q, k, v, y, pwin);
    // 6) x2 = x + y @ c_proj^T
    gemm64<<<dim3(C/64, N/64), 256>>>(y, cpw, x2, N, C, C, 1, x, nullptr, 0,0,0);
    // 7) xn2 = rms(x2)
    rmsnorm_kernel<<<N, 256>>>(x2, xn2);
    // 8) router -> rw (output tail) + top-2
    router_kernel<<<N, 256>>>(xn2, rww, out + (size_t)N*C, fe, fw);
    // 9) stable per-expert positions + counts
    pos_kernel<<<E, 1024>>>(fe, fp, cnt);
    // 10) scatter xn2 rows into expert slots
    scatter_kernel<<<N*TOPK, 256>>>(xn2, fe, fp, buf);
    // 11) h = relu(buf @ fc^T)^2 ; only occupied rows
    gemm64<<<dim3(H/64, CAP/64, E), 256>>>(buf, fcw, hbuf, CAP, H, C, 2, nullptr, cnt,
                                           (size_t)CAP*C, (size_t)H*C, (size_t)CAP*H);
    // 12) bo = h @ proj^T
    gemm64<<<dim3(C/64, CAP/64, E), 256>>>(hbuf, pjw, bo, CAP, C, H, 0, nullptr, cnt,
                                           (size_t)CAP*H, (size_t)C*H, (size_t)CAP*C);
    // 13) out = x2 + combined expert outputs
    combine_kernel<<<N, 256>>>(x2, bo, fe, fp, fw, out);
}

// round 2
// speedup vs baseline: 2.2596x; 2.2596x over previous
#include <cuda_runtime.h>
#include <math.h>

// Problem constants (fixed by setup_inputs)
constexpr int Bsz = 2;
constexpr int T   = 2048;
constexpr int C   = 1024;
constexpr int NH  = 16;
constexpr int NKV = 8;
constexpr int HD  = 64;
constexpr int E   = 8;
constexpr int H   = 2048;
constexpr int N   = Bsz * T;          // 4096
constexpr int TOPK = 2;
constexpr int CAP = 2 * N * TOPK / E; // 2048
constexpr float EPS = 1.1920929e-07f;
constexpr int QKVW = 2048;            // fused qkv row width (1024 q | 512 k | 512 v)

// -------------------- scratch (device globals; no dynamic alloc) ----------
__device__ float g_xn [N * C];
__device__ float g_qkv[N * QKVW];
__device__ float g_y  [N * C];
__device__ float g_x2 [N * C];
__device__ float g_xn2[N * C];
__device__ float g_buf[E * CAP * C];
__device__ float g_h  [E * CAP * H];
__device__ float g_bo [E * CAP * C];
__device__ int   g_fe [N * TOPK];
__device__ int   g_fp [N * TOPK];
__device__ float g_fw [N * TOPK];
__device__ int   g_cnt[E];

// -------------------- RMSNorm over C=1024, one block per row -------------
__global__ void rmsnorm_kernel(const float* __restrict__ x, float* __restrict__ xn) {
    int n = blockIdx.x, tid = threadIdx.x;  // 256 threads
    const float4* xp = (const float4*)(x + (size_t)n * C);
    float4 v = xp[tid];
    float sq = v.x*v.x + v.y*v.y + v.z*v.z + v.w*v.w;
    #pragma unroll
    for (int o = 16; o > 0; o >>= 1) sq += __shfl_xor_sync(0xffffffffu, sq, o);
    __shared__ float red[8];
    if ((tid & 31) == 0) red[tid >> 5] = sq;
    __syncthreads();
    __shared__ float tot;
    if (tid == 0) {
        float s = 0;
        #pragma unroll
        for (int i = 0; i < 8; i++) s += red[i];
        tot = s;
    }
    __syncthreads();
    float r = rsqrtf(tot / (float)C + EPS);
    float4 o4 = make_float4(v.x*r, v.y*r, v.z*r, v.w*r);
    ((float4*)(xn + (size_t)n * C))[tid] = o4;
}

// -------------------- 128x128 tiled GEMM: Cmat[M,Nn] = A[M,K] @ B[Nn,K]^T -
// mode: 0 plain, 1 add residual, 2 relu^2, 3 fused qkv (B select by column)
// expert mode when counts != nullptr: per-expert strides, M=min(counts[e],CAP)
__global__ __launch_bounds__(256, 2)
void gemm128(const float* __restrict__ A, const float* __restrict__ Bm,
             float* __restrict__ Cm, int M, int Nn, int K,
             int mode, const float* __restrict__ resid,
             const int* __restrict__ counts,
             size_t sA, size_t sB, size_t sC,
             const float* __restrict__ Bk, const float* __restrict__ Bv) {
    if (counts) {
        int e = blockIdx.z;
        A  += (size_t)e * sA;
        Bm += (size_t)e * sB;
        Cm += (size_t)e * sC;
        int cnt = counts[e];
        M = cnt < CAP ? cnt : CAP;
    }
    int row0 = blockIdx.y * 128;
    int col0 = blockIdx.x * 128;
    if (row0 >= M) return;

    const float* Bp = Bm;
    int bcol0 = col0;
    if (mode == 3) {
        if (col0 >= 1536)      { Bp = Bv; bcol0 = col0 - 1536; }
        else if (col0 >= 1024) { Bp = Bk; bcol0 = col0 - 1024; }
    }

    __shared__ float As[16 * 132];
    __shared__ float Bs[16 * 132];
    int tid = threadIdx.x;              // 256
    int tx = tid & 15, ty = tid >> 4;
    int lrow = tid >> 2, lf4 = tid & 3; // load coords

    float acc[8][8];
    #pragma unroll
    for (int i = 0; i < 8; i++)
        #pragma unroll
        for (int j = 0; j < 8; j++) acc[i][j] = 0.f;

    const float4 z4 = make_float4(0.f, 0.f, 0.f, 0.f);
    float4 pa0, pa1, pb0, pb1;
    // initial prefetch (k0 = 0)
    {
        int r0 = row0 + lrow, r1 = row0 + 64 + lrow;
        pa0 = (r0 < M) ? *(const float4*)(A + (size_t)r0 * K + lf4 * 4) : z4;
        pa1 = (r1 < M) ? *(const float4*)(A + (size_t)r1 * K + lf4 * 4) : z4;
        pb0 = *(const float4*)(Bp + (size_t)(bcol0 + lrow) * K + lf4 * 4);
        pb1 = *(const float4*)(Bp + (size_t)(bcol0 + 64 + lrow) * K + lf4 * 4);
    }

    for (int k0 = 0; k0 < K; k0 += 16) {
        // store staged tile
        As[(lf4*4+0)*132 + lrow] = pa0.x; As[(lf4*4+1)*132 + lrow] = pa0.y;
        As[(lf4*4+2)*132 + lrow] = pa0.z; As[(lf4*4+3)*132 + lrow] = pa0.w;
        As[(lf4*4+0)*132 + 64+lrow] = pa1.x; As[(lf4*4+1)*132 + 64+lrow] = pa1.y;
        As[(lf4*4+2)*132 + 64+lrow] = pa1.z; As[(lf4*4+3)*132 + 64+lrow] = pa1.w;
        Bs[(lf4*4+0)*132 + lrow] = pb0.x; Bs[(lf4*4+1)*132 + lrow] = pb0.y;
        Bs[(lf4*4+2)*132 + lrow] = pb0.z; Bs[(lf4*4+3)*132 + lrow] = pb0.w;
        Bs[(lf4*4+0)*132 + 64+lrow] = pb1.x; Bs[(lf4*4+1)*132 + 64+lrow] = pb1.y;
        Bs[(lf4*4+2)*132 + 64+lrow] = pb1.z; Bs[(lf4*4+3)*132 + 64+lrow] = pb1.w;
        __syncthreads();
        // prefetch next
        if (k0 + 16 < K) {
            int kn = k0 + 16;
            int r0 = row0 + lrow, r1 = row0 + 64 + lrow;
            pa0 = (r0 < M) ? *(const float4*)(A + (size_t)r0 * K + kn + lf4 * 4) : z4;
            pa1 = (r1 < M) ? *(const float4*)(A + (size_t)r1 * K + kn + lf4 * 4) : z4;
            pb0 = *(const float4*)(Bp + (size_t)(bcol0 + lrow) * K + kn + lf4 * 4);
            pb1 = *(const float4*)(Bp + (size_t)(bcol0 + 64 + lrow) * K + kn + lf4 * 4);
        }
        // compute
        #pragma unroll
        for (int kk = 0; kk < 16; kk++) {
            float4 a0 = *(const float4*)&As[kk*132 + ty*4];
            float4 a1 = *(const float4*)&As[kk*132 + 64 + ty*4];
            float4 b0 = *(const float4*)&Bs[kk*132 + tx*4];
            float4 b1 = *(const float4*)&Bs[kk*132 + 64 + tx*4];
            float av[8] = {a0.x,a0.y,a0.z,a0.w,a1.x,a1.y,a1.z,a1.w};
            float bv[8] = {b0.x,b0.y,b0.z,b0.w,b1.x,b1.y,b1.z,b1.w};
            #pragma unroll
            for (int i = 0; i < 8; i++)
                #pragma unroll
                for (int j = 0; j < 8; j++) acc[i][j] += av[i] * bv[j];
        }
        __syncthreads();
    }

    // epilogue
    #pragma unroll
    for (int i = 0; i < 8; i++) {
        int gr = row0 + ((i < 4) ? (ty*4 + i) : (64 + ty*4 + i - 4));
        if (gr >= M) continue;
        #pragma unroll
        for (int half = 0; half < 2; half++) {
            int gc = col0 + half*64 + tx*4;
            size_t idx = (size_t)gr * Nn + gc;
            float4 v;
            v.x = acc[i][half*4+0]; v.y = acc[i][half*4+1];
            v.z = acc[i][half*4+2]; v.w = acc[i][half*4+3];
            if (mode == 1) {
                float4 r4 = *(const float4*)(resid + idx);
                v.x += r4.x; v.y += r4.y; v.z += r4.z; v.w += r4.w;
            } else if (mode == 2) {
                v.x = v.x > 0.f ? v.x*v.x : 0.f;
                v.y = v.y > 0.f ? v.y*v.y : 0.f;
                v.z = v.z > 0.f ? v.z*v.z : 0.f;
                v.w = v.w > 0.f ? v.w*v.w : 0.f;
            }
            *(float4*)(Cm + idx) = v;
        }
    }
}

// -------------------- gate = 2*sigmoid(xn[:, :32] @ gw^T); v += gate*ve ---
__global__ void gate_kernel(const float* __restrict__ xn, const float* __restrict__ ve,
                            const float* __restrict__ gw, float* __restrict__ qkv) {
    int n = blockIdx.x, tid = threadIdx.x;   // 256
    __shared__ float g[NKV];
    int w = tid >> 5, l = tid & 31;
    float s = xn[(size_t)n * C + l] * gw[w * 32 + l];
    #pragma unroll
    for (int o = 16; o > 0; o >>= 1) s += __shfl_xor_sync(0xffffffffu, s, o);
    if (l == 0) g[w] = 2.0f / (1.0f + __expf(-s));
    __syncthreads();
    float* vrow = qkv + (size_t)n * QKVW + 1536;
    #pragma unroll
    for (int i = tid; i < NKV * HD; i += 256)
        vrow[i] += g[i >> 6] * ve[(size_t)n * (NKV * HD) + i];
}

// -------------------- RoPE then RMS over hd=64, one block per head-row ----
__global__ void rope_rms_kernel(float* __restrict__ base, int nheads,
                                const float* __restrict__ cosp, const float* __restrict__ sinp) {
    int row = blockIdx.x;
    int n = row / nheads, head = row % nheads;
    int t = n % T;
    int tid = threadIdx.x;   // 64
    __shared__ float buf[64];
    __shared__ float red[2];
    float* p = base + (size_t)n * QKVW + head * HD;
    buf[tid] = p[tid];
    __syncthreads();
    float val;
    if (tid < 32) val = buf[tid] * cosp[t * 32 + tid] + buf[tid + 32] * sinp[t * 32 + tid];
    else { int j = tid - 32; val = -buf[j] * sinp[t * 32 + j] + buf[tid] * cosp[t * 32 + j]; }
    float sq = val * val;
    #pragma unroll
    for (int o = 16; o > 0; o >>= 1) sq += __shfl_xor_sync(0xffffffffu, sq, o);
    if ((tid & 31) == 0) red[tid >> 5] = sq;
    __syncthreads();
    float r = rsqrtf((red[0] + red[1]) / (float)HD + EPS);
    p[tid] = val * r;
}

// -------------------- flash attention: 64 queries x 64-key tiles ----------
constexpr int ATTN_SMEM = (3 * 64 * 65 + 64 * 68 + 128) * 4;  // 67840 B

__global__ __launch_bounds__(256)
void attn_kernel(const float* __restrict__ qkv, float* __restrict__ y,
                 const int* __restrict__ pwin) {
    extern __shared__ float sm[];
    float* Qs  = sm;                       // [64][65]
    float* Ks  = sm + 4160;                // [64][65]
    float* Ps  = sm + 8320;                // [64][65]
    float* Vs  = sm + 12480;               // [64][68]
    float* m_s = sm + 12480 + 4352;        // [64]
    float* l_s = m_s + 64;                 // [64]

    int t0 = blockIdx.x * 64;
    int h  = blockIdx.y;
    int b  = blockIdx.z;
    int hk = h / (NH / NKV);
    int win = *pwin;
    int tid = threadIdx.x;                 // 256
    int tx = tid & 15, ty = tid >> 4;

    const float* qbase = qkv + (size_t)(b * T) * QKVW + h * HD;
    const float* kbase = qkv + (size_t)(b * T) * QKVW + 1024 + hk * HD;
    const float* vbase = qkv + (size_t)(b * T) * QKVW + 1536 + hk * HD;

    // load Q tile (transposed-free natural layout, pad 65)
    #pragma unroll
    for (int s = 0; s < 4; s++) {
        int id = tid + 256 * s;
        int c = id >> 4, d4 = id & 15;
        float4 v4 = *(const float4*)(qbase + (size_t)(t0 + c) * QKVW + d4 * 4);
        Qs[c*65 + d4*4 + 0] = v4.x; Qs[c*65 + d4*4 + 1] = v4.y;
        Qs[c*65 + d4*4 + 2] = v4.z; Qs[c*65 + d4*4 + 3] = v4.w;
    }
    if (tid < 64) { m_s[tid] = -1e30f; l_s[tid] = 0.f; }
    float o[4][4];
    #pragma unroll
    for (int i = 0; i < 4; i++)
        #pragma unroll
        for (int j = 0; j < 4; j++) o[i][j] = 0.f;
    __syncthreads();

    int kt0 = t0 - win; if (kt0 < 0) kt0 = 0; kt0 &= ~63;
    for (int kt = kt0; kt <= t0; kt += 64) {
        // load K, V tiles
        #pragma unroll
        for (int s = 0; s < 4; s++) {
            int id = tid + 256 * s;
            int c = id >> 4, d4 = id & 15;
            float4 k4 = *(const float4*)(kbase + (size_t)(kt + c) * QKVW + d4 * 4);
            Ks[c*65 + d4*4 + 0] = k4.x; Ks[c*65 + d4*4 + 1] = k4.y;
            Ks[c*65 + d4*4 + 2] = k4.z; Ks[c*65 + d4*4 + 3] = k4.w;
            float4 v4 = *(const float4*)(vbase + (size_t)(kt + c) * QKVW + d4 * 4);
            *(float4*)&Vs[c*68 + d4*4] = v4;
        }
        __syncthreads();

        // S = Q @ K^T (each thread 4x4)
        float sacc[4][4];
        #pragma unroll
        for (int i = 0; i < 4; i++)
            #pragma unroll
            for (int j = 0; j < 4; j++) sacc[i][j] = 0.f;
        #pragma unroll 8
        for (int d = 0; d < 64; d++) {
            float qv[4], kv[4];
            #pragma unroll
            for (int i = 0; i < 4; i++) qv[i] = Qs[(ty*4 + i)*65 + d];
            #pragma unroll
            for (int j = 0; j < 4; j++) kv[j] = Ks[(tx*4 + j)*65 + d];
            #pragma unroll
            for (int i = 0; i < 4; i++)
                #pragma unroll
                for (int j = 0; j < 4; j++) sacc[i][j] += qv[i] * kv[j];
        }

        // mask + online softmax update
        float scl[4];
        float mrow[4], rsum[4];
        #pragma unroll
        for (int i = 0; i < 4; i++) {
            int gi = t0 + ty*4 + i;
            float mx = -1e30f;
            #pragma unroll
            for (int j = 0; j < 4; j++) {
                int gj = kt + tx*4 + j;
                float v = sacc[i][j] * 0.125f;
                bool valid = (gj <= gi) && (gi - gj <= win);
                v = valid ? v : -1e30f;
                sacc[i][j] = v;
                mx = fmaxf(mx, v);
            }
            #pragma unroll
            for (int s = 1; s < 16; s <<= 1) mx = fmaxf(mx, __shfl_xor_sync(0xffffffffu, mx, s));
            float mo = m_s[ty*4 + i];
            float mn = fmaxf(mo, mx);
            scl[i] = __expf(mo - mn);
            float rs = 0.f;
            #pragma unroll
            for (int j = 0; j < 4; j++) {
                float p = __expf(sacc[i][j] - mn);
                sacc[i][j] = p;
                rs += p;
            }
            #pragma unroll
            for (int s = 1; s < 16; s <<= 1) rs += __shfl_xor_sync(0xffffffffu, rs, s);
            mrow[i] = mn; rsum[i] = rs;
        }
        if (tx == 0) {
            #pragma unroll
            for (int i = 0; i < 4; i++) {
                m_s[ty*4 + i] = mrow[i];
                l_s[ty*4 + i] = l_s[ty*4 + i] * scl[i] + rsum[i];
            }
        }
        // write P
        #pragma unroll
        for (int i = 0; i < 4; i++)
            #pragma unroll
            for (int j = 0; j < 4; j++)
                Ps[(ty*4 + i)*65 + tx*4 + j] = sacc[i][j];
        __syncthreads();

        // O = O*scale + P @ V
        #pragma unroll
        for (int i = 0; i < 4; i++)
            #pragma unroll
            for (int j = 0; j < 4; j++) o[i][j] *= scl[i];
        #pragma unroll 8
        for (int s = 0; s < 64; s++) {
            float pv[4];
            #pragma unroll
            for (int i = 0; i < 4; i++) pv[i] = Ps[(ty*4 + i)*65 + s];
            float4 vv = *(const float4*)&Vs[s*68 + tx*4];
            #pragma unroll
            for (int i = 0; i < 4; i++) {
                o[i][0] += pv[i] * vv.x;
                o[i][1] += pv[i] * vv.y;
                o[i][2] += pv[i] * vv.z;
                o[i][3] += pv[i] * vv.w;
            }
        }
        __syncthreads();
    }

    // final normalize + store
    #pragma unroll
    for (int i = 0; i < 4; i++) {
        int gr = t0 + ty*4 + i;
        float inv = 1.0f / l_s[ty*4 + i];
        float4 r4 = make_float4(o[i][0]*inv, o[i][1]*inv, o[i][2]*inv, o[i][3]*inv);
        *(float4*)(y + (size_t)(b*T + gr) * C + h * HD + tx * 4) = r4;
    }
}

// -------------------- router: logits, softmax -> rw out, top-2 ------------
__global__ void router_kernel(const float* __restrict__ xn2, const float* __restrict__ rw_w,
                              float* __restrict__ rw_out, int* __restrict__ flat_e,
                              float* __restrict__ flat_w) {
    int n = blockIdx.x, tid = threadIdx.x;   // 256
    int w = tid >> 5, l = tid & 31;
    __shared__ float logit[E];
    const float* xp = xn2 + (size_t)n * C;
    float s = 0.f;
    for (int i = l; i < C; i += 32) s += xp[i] * rw_w[(size_t)w * C + i];
    #pragma unroll
    for (int o = 16; o > 0; o >>= 1) s += __shfl_xor_sync(0xffffffffu, s, o);
    if (l == 0) logit[w] = s;
    __syncthreads();
    if (tid == 0) {
        float m = -1e30f;
        #pragma unroll
        for (int e = 0; e < E; e++) m = fmaxf(m, logit[e]);
        float p[E], sum = 0.f;
        #pragma unroll
        for (int e = 0; e < E; e++) { p[e] = __expf(logit[e] - m); sum += p[e]; }
        float inv = 1.0f / sum;
        #pragma unroll
        for (int e = 0; e < E; e++) { p[e] *= inv; rw_out[(size_t)n * E + e] = p[e]; }
        int b0 = 0; float v0 = p[0];
        #pragma unroll
        for (int e = 1; e < E; e++) if (p[e] > v0) { v0 = p[e]; b0 = e; }
        int b1 = -1; float v1 = -1.f;
        #pragma unroll
        for (int e = 0; e < E; e++) if (e != b0 && p[e] > v1) { v1 = p[e]; b1 = e; }
        float wsum = v0 + v1 + 1e-10f;
        flat_e[2 * n]     = b0; flat_w[2 * n]     = v0 / wsum;
        flat_e[2 * n + 1] = b1; flat_w[2 * n + 1] = v1 / wsum;
    }
}

// -------------------- per-expert stable positions (prefix scan) -----------
__global__ void pos_kernel(const int* __restrict__ flat_e, int* __restrict__ flat_pos,
                           int* __restrict__ counts) {
    int e = blockIdx.x;       // one block per expert
    int tid = threadIdx.x;    // 1024, each handles 8 flats
    __shared__ int sd[1024];
    int base_f = tid * 8;
    int loc = 0;
    #pragma unroll
    for (int i = 0; i < 8; i++) loc += (flat_e[base_f + i] == e);
    sd[tid] = loc; __syncthreads();
    for (int o = 1; o < 1024; o <<= 1) {
        int v = 0;
        if (tid >= o) v = sd[tid - o];
        __syncthreads();
        sd[tid] += v;
        __syncthreads();
    }
    int running = sd[tid] - loc;
    #pragma unroll
    for (int i = 0; i < 8; i++)
        if (flat_e[base_f + i] == e) flat_pos[base_f + i] = running++;
    if (tid == 1023) counts[e] = sd[1023];
}

// -------------------- scatter token rows into expert buffers --------------
__global__ void scatter_kernel(const float* __restrict__ xn2, const int* __restrict__ flat_e,
                               const int* __restrict__ flat_pos, float* __restrict__ buf) {
    int f = blockIdx.x, tid = threadIdx.x;  // 256
    int pos = flat_pos[f];
    if (pos >= CAP) return;
    int e = flat_e[f], token = f >> 1;
    const float4* src = (const float4*)(xn2 + (size_t)token * C);
    float4* dst = (float4*)(buf + ((size_t)e * CAP + pos) * C);
    dst[tid] = src[tid];
}

// -------------------- combine expert outputs + residual -> final out ------
__global__ void combine_kernel(const float* __restrict__ x2, const float* __restrict__ bo,
                               const int* __restrict__ flat_e, const int* __restrict__ flat_pos,
                               const float* __restrict__ flat_w, float* __restrict__ out) {
    int n = blockIdx.x, tid = threadIdx.x;  // 256
    float4 acc = ((const float4*)(x2 + (size_t)n * C))[tid];
    #pragma unroll
    for (int kk = 0; kk < TOPK; kk++) {
        int f = TOPK * n + kk;
        int pos = flat_pos[f];
        if (pos >= CAP) continue;
        float wgt = flat_w[f];
        float4 bv = ((const float4*)(bo + ((size_t)flat_e[f] * CAP + pos) * C))[tid];
        acc.x += wgt * bv.x; acc.y += wgt * bv.y; acc.z += wgt * bv.z; acc.w += wgt * bv.w;
    }
    ((float4*)(out + (size_t)n * C))[tid] = acc;
}

// ==========================================================================
extern "C" void kernel_launch(void* const* d_in, const int* in_sizes, int n_in,
                              void* d_out, int out_size) {
    const float* x    = (const float*)d_in[0];
    const float* ve   = (const float*)d_in[1];
    const float* cosp = (const float*)d_in[2];
    const float* sinp = (const float*)d_in[3];
    const float* cqw  = (const float*)d_in[4];
    const float* ckw  = (const float*)d_in[5];
    const float* cvw  = (const float*)d_in[6];
    const float* cpw  = (const float*)d_in[7];
    const float* gww  = (const float*)d_in[8];
    const float* rww  = (const float*)d_in[9];
    const float* fcw  = (const float*)d_in[10];
    const float* pjw  = (const float*)d_in[11];
    const int*   pwin = (const int*)d_in[12];
    float* out = (float*)d_out;

    float *xn, *qkv, *y, *x2, *xn2, *buf, *hbuf, *bo, *fw;
    int *fe, *fp, *cnt;
    cudaGetSymbolAddress((void**)&xn,  g_xn);
    cudaGetSymbolAddress((void**)&qkv, g_qkv);
    cudaGetSymbolAddress((void**)&y,   g_y);
    cudaGetSymbolAddress((void**)&x2,  g_x2);
    cudaGetSymbolAddress((void**)&xn2, g_xn2);
    cudaGetSymbolAddress((void**)&buf, g_buf);
    cudaGetSymbolAddress((void**)&hbuf,g_h);
    cudaGetSymbolAddress((void**)&bo,  g_bo);
    cudaGetSymbolAddress((void**)&fe,  g_fe);
    cudaGetSymbolAddress((void**)&fp,  g_fp);
    cudaGetSymbolAddress((void**)&fw,  g_fw);
    cudaGetSymbolAddress((void**)&cnt, g_cnt);

    cudaFuncSetAttribute(attn_kernel, cudaFuncAttributeMaxDynamicSharedMemorySize, ATTN_SMEM);

    // 1) xn = rms(x)
    rmsnorm_kernel<<<N, 256>>>(x, xn);
    // 2) fused qkv projection: qkv[N][2048] = xn @ [cq|ck|cv]^T
    gemm128<<<dim3(QKVW/128, N/128), 256>>>(xn, cqw, qkv, N, QKVW, C, 3, nullptr,
                                            nullptr, 0,0,0, ckw, cvw);
    // 3) v += gate * ve
    gate_kernel<<<N, 256>>>(xn, ve, gww, qkv);
    // 4) rope + rms on q, k
    rope_rms_kernel<<<N*NH,  64>>>(qkv,        NH,  cosp, sinp);
    rope_rms_kernel<<<N*NKV, 64>>>(qkv + 1024, NKV, cosp, sinp);
    // 5) flash attention
    attn_kernel<<<dim3(T/64, NH, Bsz), 256, ATTN_SMEM>>>(qkv, y, pwin);
    // 6) x2 = x + y @ c_proj^T
    gemm128<<<dim3(C/128, N/128), 256>>>(y, cpw, x2, N, C, C, 1, x,
                                         nullptr, 0,0,0, nullptr, nullptr);
    // 7) xn2 = rms(x2)
    rmsnorm_kernel<<<N, 256>>>(x2, xn2);
    // 8) router -> rw (output tail) + top-2
    router_kernel<<<N, 256>>>(xn2, rww, out + (size_t)N*C, fe, fw);
    // 9) stable per-expert positions + counts
    pos_kernel<<<E, 1024>>>(fe, fp, cnt);
    // 10) scatter xn2 rows into expert slots
    scatter_kernel<<<N*TOPK, 256>>>(xn2, fe, fp, buf);
    // 11) h = relu(buf @ fc^T)^2 ; only occupied rows
    gemm128<<<dim3(H/128, CAP/128, E), 256>>>(buf, fcw, hbuf, CAP, H, C, 2, nullptr, cnt,
                                              (size_t)CAP*C, (size_t)H*C, (size_t)CAP*H,
                                              nullptr, nullptr);
    // 12) bo = h @ proj^T
    gemm128<<<dim3(C/128, CAP/128, E), 256>>>(hbuf, pjw, bo, CAP, C, H, 0, nullptr, cnt,
                                              (size_t)CAP*H, (size_t)C*H, (size_t)CAP*C,
                                              nullptr, nullptr);
    // 13) out = x2 + combined expert outputs
    combine_kernel<<<N, 256>>>(x2, bo, fe, fp, fw, out);
}